// round 1
// baseline (speedup 1.0000x reference)
#include <cuda_runtime.h>
#include <math.h>

// ContrastiveLoss: total = sum over strict lower triangle of masked hinge losses
// on pairwise distances of row-normalized embeddings, divided by n(n-1)/2.
//
// Pipeline:
//   prep_kernel:  normalize rows of E, compute s=sum(e^2), r=sum(e) per row,
//                 detect label dtype (int32 vs int64 storage).
//   pair_kernel:  triangular tiled fp32 GEMM (64x64 tiles, BK=16) computing
//                 dot(e_i, e_j) with fused distance/loss epilogue; per-block
//                 partial sums in double (deterministic, no atomics).
//   finalize:     fixed-order reduce partials, scale, write scalar.

#define D     256
#define N_MAX 8192
#define EPSV  1e-6f
#define BM    64
#define BN    64
#define BK    16

__device__ float  g_e[N_MAX * D];
__device__ float  g_s[N_MAX];
__device__ float  g_r[N_MAX];
__device__ int    g_is64;
__device__ double g_part[((N_MAX / 64) * (N_MAX / 64 + 1)) / 2 + 64];

// ---------------------------------------------------------------------------
// prep: one block per row, 256 threads (= D)
// ---------------------------------------------------------------------------
__global__ void prep_kernel(const float* __restrict__ x,
                            const int* __restrict__ lab32, int n) {
    int i = blockIdx.x;
    int t = threadIdx.x;

    float v  = x[i * D + t];
    float ss = v * v;
    float sv = v;
#pragma unroll
    for (int o = 16; o > 0; o >>= 1) {
        ss += __shfl_xor_sync(0xffffffffu, ss, o);
        sv += __shfl_xor_sync(0xffffffffu, sv, o);
    }
    __shared__ float sh_ss[8], sh_sv[8];
    if ((t & 31) == 0) { sh_ss[t >> 5] = ss; sh_sv[t >> 5] = sv; }
    __syncthreads();
    float tss = 0.f, tsv = 0.f;
#pragma unroll
    for (int k = 0; k < 8; k++) { tss += sh_ss[k]; tsv += sh_sv[k]; }

    float nrm = sqrtf(tss);
    float inv = 1.0f / fmaxf(nrm, EPSV);
    g_e[i * D + t] = v * inv;
    if (t == 0) {
        g_s[i] = tss * inv * inv;   // == sum(e*e)
        g_r[i] = tsv * inv;         // == sum(e)
    }

    // Label dtype sniff (block 0 only). If labels are stored as int64, the
    // high 32-bit word of each label is 0. Checking only the first n/2
    // labels keeps all reads in-bounds under BOTH interpretations
    // (int32 buffer has n words; we touch indices < n).
    if (i == 0) {
        __shared__ int sh_ok;
        if (t == 0) sh_ok = 1;
        __syncthreads();
        int ok = 1;
        for (int idx = t; idx < n / 2; idx += 256) {
            if (lab32[2 * idx + 1] != 0) ok = 0;
        }
        if (!ok) atomicAnd(&sh_ok, 0);
        __syncthreads();
        if (t == 0) g_is64 = sh_ok;
    }
}

// ---------------------------------------------------------------------------
// pair: triangular blocks, 64x64 tile per block, 256 threads, 4x4 microtile
// ---------------------------------------------------------------------------
__global__ void __launch_bounds__(256)
pair_kernel(const int* __restrict__ lab32, int n) {
    __shared__ float As[BK][BM];
    __shared__ float Bs[BK][BN];

    long long L  = blockIdx.x;
    int bi = (int)((-1.0 + sqrt(1.0 + 8.0 * (double)L)) * 0.5);
    while ((long long)bi * (bi + 1) / 2 > L) bi--;
    while ((long long)(bi + 1) * (bi + 2) / 2 <= L) bi++;
    int bj = (int)(L - (long long)bi * (bi + 1) / 2);
    int i0 = bi * BM;
    int j0 = bj * BN;

    int tid = threadIdx.x;
    int tr  = tid >> 4;          // 0..15 (output row group)
    int tc  = tid & 15;          // 0..15 (output col group)
    int lr  = tid >> 2;          // 0..63 (load row)
    int lk  = (tid & 3) << 2;    // 0,4,8,12 (load k offset)

    int arow = min(i0 + lr, n - 1);
    int brow = min(j0 + lr, n - 1);

    float acc[4][4] = {};

    for (int k0 = 0; k0 < D; k0 += BK) {
        float4 a = *(const float4*)&g_e[arow * D + k0 + lk];
        float4 b = *(const float4*)&g_e[brow * D + k0 + lk];
        As[lk + 0][lr] = a.x; As[lk + 1][lr] = a.y;
        As[lk + 2][lr] = a.z; As[lk + 3][lr] = a.w;
        Bs[lk + 0][lr] = b.x; Bs[lk + 1][lr] = b.y;
        Bs[lk + 2][lr] = b.z; Bs[lk + 3][lr] = b.w;
        __syncthreads();
#pragma unroll
        for (int k = 0; k < BK; k++) {
            float4 ra = *(const float4*)&As[k][tr << 2];
            float4 rb = *(const float4*)&Bs[k][tc << 2];
            float va[4] = {ra.x, ra.y, ra.z, ra.w};
            float vb[4] = {rb.x, rb.y, rb.z, rb.w};
#pragma unroll
            for (int m = 0; m < 4; m++)
#pragma unroll
                for (int c = 0; c < 4; c++)
                    acc[m][c] = fmaf(va[m], vb[c], acc[m][c]);
        }
        __syncthreads();
    }

    // ---- fused epilogue ----
    int is64 = g_is64;
    float si[4], ri[4], sj[4], rj[4];
    int   li[4], lj[4];
#pragma unroll
    for (int m = 0; m < 4; m++) {
        int I  = i0 + (tr << 2) + m;
        int Ic = min(I, n - 1);
        si[m] = g_s[Ic];
        ri[m] = g_r[Ic];
        li[m] = lab32[is64 ? 2 * Ic : Ic];
    }
#pragma unroll
    for (int c = 0; c < 4; c++) {
        int J  = j0 + (tc << 2) + c;
        int Jc = min(J, n - 1);
        sj[c] = g_s[Jc];
        rj[c] = g_r[Jc];
        lj[c] = lab32[is64 ? 2 * Jc : Jc];
    }

    float lsum = 0.f;
#pragma unroll
    for (int m = 0; m < 4; m++) {
#pragma unroll
        for (int c = 0; c < 4; c++) {
            int I = i0 + (tr << 2) + m;
            int J = j0 + (tc << 2) + c;
            if (I > J && I < n) {
                float dist2 = si[m] + sj[c] - 2.0f * acc[m][c]
                            + 2.0f * EPSV * (ri[m] - rj[c])
                            + (float)D * EPSV * EPSV;
                float dist = sqrtf(fmaxf(dist2, 1e-12f));
                float loss;
                if (li[m] == lj[c]) {
                    float p = fmaxf(dist - 0.1f, 0.0f);
                    loss = 0.5f * p * p;
                } else {
                    float boost = (I == J + 1 && li[m] == 1) ? 2.0f : 1.0f;
                    float q = fmaxf(1.0f - dist, 0.0f);
                    loss = 0.5f * boost * q * q;
                }
                lsum += loss;
            }
        }
    }

    // deterministic block reduction in double, one partial per block
    double dsum = (double)lsum;
#pragma unroll
    for (int o = 16; o > 0; o >>= 1)
        dsum += __shfl_xor_sync(0xffffffffu, dsum, o);
    __shared__ double sh_d[8];
    if ((tid & 31) == 0) sh_d[tid >> 5] = dsum;
    __syncthreads();
    if (tid == 0) {
        double tot = 0.0;
#pragma unroll
        for (int w = 0; w < 8; w++) tot += sh_d[w];
        g_part[blockIdx.x] = tot;
    }
}

// ---------------------------------------------------------------------------
// finalize: fixed-order reduction of block partials
// ---------------------------------------------------------------------------
__global__ void finalize_kernel(float* __restrict__ out, int n, int nblocks) {
    int t = threadIdx.x;
    double s = 0.0;
    for (int i = t; i < nblocks; i += 256) s += g_part[i];
#pragma unroll
    for (int o = 16; o > 0; o >>= 1)
        s += __shfl_xor_sync(0xffffffffu, s, o);
    __shared__ double sh[8];
    if ((t & 31) == 0) sh[t >> 5] = s;
    __syncthreads();
    if (t == 0) {
        double tot = 0.0;
#pragma unroll
        for (int w = 0; w < 8; w++) tot += sh[w];
        double ncomp = 0.5 * (double)n * (double)(n - 1);
        out[0] = (float)(tot / ncomp);
    }
}

// ---------------------------------------------------------------------------
extern "C" void kernel_launch(void* const* d_in, const int* in_sizes, int n_in,
                              void* d_out, int out_size) {
    const float* emb  = (const float*)d_in[0];
    const int*   lab  = (const int*)d_in[1];   // int32 view; dtype sniffed on-device
    int n = in_sizes[0] / D;

    prep_kernel<<<n, 256>>>(emb, lab, n);

    int nb = (n + BM - 1) / BM;
    int nblocks = nb * (nb + 1) / 2;
    pair_kernel<<<nblocks, 256>>>(lab, n);

    finalize_kernel<<<1, 256>>>((float*)d_out, n, nblocks);
}

// round 3
// speedup vs baseline: 3.8868x; 3.8868x over previous
#include <cuda_runtime.h>
#include <cuda_bf16.h>
#include <math.h>
#include <stdint.h>

// ContrastiveLoss via warp-level bf16 HMMA (mma.sync.m16n8k16, sm_80+ path —
// tcgen05 is rejected by this build's base-sm_103 PTX target).
//
//  prep_kernel : normalize rows (fp32), emit bf16 E, s=sum(e^2), r=sum(e),
//                label-dtype sniff (int64 vs int32 storage).
//  pair_kernel : persistent (grid=148). Each CTA loops over triangular
//                128x128 tiles: LDG -> XOR-swizzled STS, 16 k-steps of
//                ldmatrix.x4 + mma.sync bf16 (32x64 warp tiles), fused
//                distance/hinge epilogue on register fragments, per-CTA
//                double accumulator (deterministic).
//  finalize    : fixed-order reduce partials, scale by n(n-1)/2.

#define D      256
#define N_MAX  8192
#define EPSV   1e-6f
#define TM     128
#define GRID_PAIR 148

__device__ __nv_bfloat16 g_ebf[N_MAX * D];
__device__ float  g_s[N_MAX];
__device__ float  g_r[N_MAX];
__device__ int    g_is64;
__device__ double g_part[GRID_PAIR];

__device__ __forceinline__ uint32_t smem_u32(const void* p) {
    uint32_t a;
    asm("{ .reg .u64 t; cvta.to.shared.u64 t, %1; cvt.u32.u64 %0, t; }"
        : "=r"(a) : "l"(p));
    return a;
}
__device__ __forceinline__ void ldsm4(uint32_t* r, uint32_t a) {
    asm volatile("ldmatrix.sync.aligned.m8n8.x4.shared.b16 {%0,%1,%2,%3}, [%4];"
                 : "=r"(r[0]), "=r"(r[1]), "=r"(r[2]), "=r"(r[3]) : "r"(a));
}
__device__ __forceinline__ void mma16816(float* c, const uint32_t* a,
                                         uint32_t b0, uint32_t b1) {
    asm volatile(
        "mma.sync.aligned.m16n8k16.row.col.f32.bf16.bf16.f32 "
        "{%0,%1,%2,%3}, {%4,%5,%6,%7}, {%8,%9}, {%0,%1,%2,%3};"
        : "+f"(c[0]), "+f"(c[1]), "+f"(c[2]), "+f"(c[3])
        : "r"(a[0]), "r"(a[1]), "r"(a[2]), "r"(a[3]), "r"(b0), "r"(b1));
}

// ---------------------------------------------------------------------------
// prep: 8 warps/block, one row per warp
// ---------------------------------------------------------------------------
__global__ void prep_kernel(const float* __restrict__ x,
                            const int* __restrict__ lab32, int n) {
    int wid = threadIdx.x >> 5, lid = threadIdx.x & 31;
    int row = blockIdx.x * 8 + wid;
    if (row < n) {
        const float4* src = (const float4*)&x[row * D + lid * 8];
        float4 a = src[0], b = src[1];
        float ss = a.x*a.x + a.y*a.y + a.z*a.z + a.w*a.w
                 + b.x*b.x + b.y*b.y + b.z*b.z + b.w*b.w;
        float sv = a.x + a.y + a.z + a.w + b.x + b.y + b.z + b.w;
#pragma unroll
        for (int o = 16; o > 0; o >>= 1) {
            ss += __shfl_xor_sync(0xffffffffu, ss, o);
            sv += __shfl_xor_sync(0xffffffffu, sv, o);
        }
        float inv = 1.0f / fmaxf(sqrtf(ss), EPSV);
        __nv_bfloat162 w0 = __nv_bfloat162(__float2bfloat16(a.x*inv), __float2bfloat16(a.y*inv));
        __nv_bfloat162 w1 = __nv_bfloat162(__float2bfloat16(a.z*inv), __float2bfloat16(a.w*inv));
        __nv_bfloat162 w2 = __nv_bfloat162(__float2bfloat16(b.x*inv), __float2bfloat16(b.y*inv));
        __nv_bfloat162 w3 = __nv_bfloat162(__float2bfloat16(b.z*inv), __float2bfloat16(b.w*inv));
        uint4 pk;
        pk.x = *(uint32_t*)&w0; pk.y = *(uint32_t*)&w1;
        pk.z = *(uint32_t*)&w2; pk.w = *(uint32_t*)&w3;
        *(uint4*)&g_ebf[row * D + lid * 8] = pk;
        if (lid == 0) {
            g_s[row] = ss * inv * inv;
            g_r[row] = sv * inv;
        }
    }
    // label dtype sniff (block 0): int64 storage iff all high words are 0.
    // Only first n/2 labels checked -> in-bounds under both interpretations.
    if (blockIdx.x == 0) {
        __shared__ int sh_ok;
        if (threadIdx.x == 0) sh_ok = 1;
        __syncthreads();
        int ok = 1;
        for (int idx = threadIdx.x; idx < n / 2; idx += blockDim.x)
            if (lab32[2 * idx + 1] != 0) ok = 0;
        if (!ok) atomicAnd(&sh_ok, 0);
        __syncthreads();
        if (threadIdx.x == 0) g_is64 = sh_ok;
    }
}

// ---------------------------------------------------------------------------
// pair: persistent, 256 threads (8 warps), 128x128 tile, 32x64 warp tiles
// ---------------------------------------------------------------------------
__global__ void __launch_bounds__(256, 1)
pair_kernel(const int* __restrict__ lab32, int n, int ntiles) {
    extern __shared__ char sm[];
    const uint32_t Abase = smem_u32(sm);
    const uint32_t Bbase = Abase + 65536;
    float* civ  = (float*)(sm + 131072);
    float* cjv  = (float*)(sm + 131072 + 512);
    int*   labi = (int*)  (sm + 131072 + 1024);
    int*   labj = (int*)  (sm + 131072 + 1536);

    const int tid = threadIdx.x, wid = tid >> 5, lid = tid & 31;
    const int warp_m = wid >> 1, warp_n = wid & 1;     // 4 x 2 warp grid
    const int q = lid >> 3, rl = lid & 7;
    const int qh = q >> 1, ql = q & 1;
    const int is64 = g_is64;

    // per-lane ldmatrix row precompute
    uint32_t rowA[2], r7A[2];                          // mt = 0,1
#pragma unroll
    for (int mt = 0; mt < 2; mt++) {
        int r = warp_m * 32 + mt * 16 + ql * 8 + rl;   // A: row add = (q&1)*8
        rowA[r7A[mt] = 0, mt] = 0;                     // placate compiler
        rowA[mt] = (uint32_t)r * 512u;
        r7A[mt]  = (uint32_t)(r & 7);
    }
    uint32_t rowB[4], r7B[4];                          // pair = 0..3
#pragma unroll
    for (int p = 0; p < 4; p++) {
        int r = warp_n * 64 + p * 16 + qh * 8 + rl;    // B: row add = (q>>1)*8
        rowB[p] = (uint32_t)r * 512u;
        r7B[p]  = (uint32_t)(r & 7);
    }

    double acc = 0.0;
    for (int t = blockIdx.x; t < ntiles; t += gridDim.x) {
        int bi = (int)((sqrtf(8.0f * (float)t + 1.0f) - 1.0f) * 0.5f);
        while ((bi + 1) * (bi + 2) / 2 <= t) bi++;
        while (bi * (bi + 1) / 2 > t) bi--;
        int bj = t - bi * (bi + 1) / 2;
        int i0 = bi * TM, j0 = bj * TM;

        __syncthreads();   // previous tile fully consumed (SMEM reuse)

        // stage A/B tiles: 128 rows x 32 chunks(16B), swizzle c ^= r&7
#pragma unroll
        for (int k = 0; k < 16; k++) {
            int idx = tid + (k << 8);          // 0..4095
            int r = idx >> 5, c = idx & 31;
            uint32_t soff = (uint32_t)r * 512u + (uint32_t)((c ^ (r & 7)) << 4);
            int ra = min(i0 + r, n - 1);
            int rb = min(j0 + r, n - 1);
            *(uint4*)(sm + soff)           = *(const uint4*)&g_ebf[ra * D + (c << 3)];
            *(uint4*)(sm + 65536 + soff)   = *(const uint4*)&g_ebf[rb * D + (c << 3)];
        }
        // row/col stats
        if (tid < 128) {
            int I = min(i0 + tid, n - 1);
            civ[tid]  = g_s[I] + 2.0f * EPSV * g_r[I] + (float)D * EPSV * EPSV;
            labi[tid] = lab32[is64 ? 2 * I : I];
        } else {
            int jj = tid - 128;
            int J = min(j0 + jj, n - 1);
            cjv[jj]  = g_s[J] - 2.0f * EPSV * g_r[J];
            labj[jj] = lab32[is64 ? 2 * J : J];
        }
        __syncthreads();

        // ---- HMMA mainloop: 16 k-steps ----
        float cacc[2][8][4];
#pragma unroll
        for (int mt = 0; mt < 2; mt++)
#pragma unroll
            for (int nt = 0; nt < 8; nt++)
#pragma unroll
                for (int e = 0; e < 4; e++) cacc[mt][nt][e] = 0.0f;

#pragma unroll
        for (int ks = 0; ks < 16; ks++) {
            const uint32_t cb = (uint32_t)(ks << 1);
            uint32_t Af[2][4];
#pragma unroll
            for (int mt = 0; mt < 2; mt++)
                ldsm4(Af[mt], Abase + rowA[mt] + (((cb + qh) ^ r7A[mt]) << 4));
#pragma unroll
            for (int p = 0; p < 4; p++) {
                uint32_t Bf[4];
                ldsm4(Bf, Bbase + rowB[p] + (((cb + ql) ^ r7B[p]) << 4));
                mma16816(cacc[0][2 * p],     Af[0], Bf[0], Bf[1]);
                mma16816(cacc[1][2 * p],     Af[1], Bf[0], Bf[1]);
                mma16816(cacc[0][2 * p + 1], Af[0], Bf[2], Bf[3]);
                mma16816(cacc[1][2 * p + 1], Af[1], Bf[2], Bf[3]);
            }
        }

        // ---- fused epilogue on register fragments ----
        // c0,c1: row = lid>>2,   cols (lid&3)*2, +1
        // c2,c3: row = lid>>2+8, same cols
        float lsum = 0.0f;
        const int rbase = (lid >> 2), cbase = (lid & 3) << 1;
#pragma unroll
        for (int mt = 0; mt < 2; mt++) {
#pragma unroll
            for (int half = 0; half < 2; half++) {
                int ii = warp_m * 32 + mt * 16 + rbase + half * 8;
                int I  = i0 + ii;
                float ci = civ[ii];
                int   li = labi[ii];
#pragma unroll
                for (int nt = 0; nt < 8; nt++) {
#pragma unroll
                    for (int e = 0; e < 2; e++) {
                        int jj = warp_n * 64 + nt * 8 + cbase + e;
                        int J  = j0 + jj;
                        float g = cacc[mt][nt][half * 2 + e];
                        float dist2 = ci + cjv[jj] - 2.0f * g;
                        float dist  = sqrtf(fmaxf(dist2, 1e-12f));
                        float loss;
                        if (li == labj[jj]) {
                            float p = fmaxf(dist - 0.1f, 0.0f);
                            loss = 0.5f * p * p;
                        } else {
                            float b = (I == J + 1 && li == 1) ? 2.0f : 1.0f;
                            float qq = fmaxf(1.0f - dist, 0.0f);
                            loss = 0.5f * b * qq * qq;
                        }
                        if (I > J && I < n) lsum += loss;
                    }
                }
            }
        }
        acc += (double)lsum;
    }

    // deterministic reduction: warp shfl (double) then smem
#pragma unroll
    for (int o = 16; o > 0; o >>= 1)
        acc += __shfl_xor_sync(0xffffffffu, acc, o);
    __shared__ double sh_d[8];
    if (lid == 0) sh_d[wid] = acc;
    __syncthreads();
    if (tid == 0) {
        double tot = 0.0;
#pragma unroll
        for (int w = 0; w < 8; w++) tot += sh_d[w];
        g_part[blockIdx.x] = tot;
    }
}

// ---------------------------------------------------------------------------
__global__ void finalize_kernel(float* __restrict__ out, int n, int nparts) {
    int t = threadIdx.x;
    double s = 0.0;
    for (int i = t; i < nparts; i += 256) s += g_part[i];
#pragma unroll
    for (int o = 16; o > 0; o >>= 1)
        s += __shfl_xor_sync(0xffffffffu, s, o);
    __shared__ double sh[8];
    if ((t & 31) == 0) sh[t >> 5] = s;
    __syncthreads();
    if (t == 0) {
        double tot = 0.0;
#pragma unroll
        for (int w = 0; w < 8; w++) tot += sh[w];
        out[0] = (float)(tot / (0.5 * (double)n * (double)(n - 1)));
    }
}

// ---------------------------------------------------------------------------
extern "C" void kernel_launch(void* const* d_in, const int* in_sizes, int n_in,
                              void* d_out, int out_size) {
    const float* emb = (const float*)d_in[0];
    const int*   lab = (const int*)d_in[1];   // dtype sniffed on-device
    int n = in_sizes[0] / D;

    const int smem_bytes = 131072 + 2048;
    cudaFuncSetAttribute(pair_kernel, cudaFuncAttributeMaxDynamicSharedMemorySize, smem_bytes);

    prep_kernel<<<(n + 7) / 8, 256>>>(emb, lab, n);

    int nb = (n + TM - 1) / TM;
    int ntiles = nb * (nb + 1) / 2;
    int gp = min(GRID_PAIR, ntiles);
    pair_kernel<<<gp, 256, smem_bytes>>>(lab, n, ntiles);

    finalize_kernel<<<1, 256>>>((float*)d_out, n, gp);
}